// round 12
// baseline (speedup 1.0000x reference)
#include <cuda_runtime.h>
#include <math.h>

// Q_MultiHeadedAttention: quantum attention collapsed to 2x2 Heisenberg
// algebra. 16 lanes: i = lane>>2 (query row 0..3), t = lane&3 (output qubit,
// t==3 pads). No cross-lane communication (R6 showed SHFL on the critical
// path regresses at this launch-floor-bound scale). Session-best measured
// configuration (ncu 3.840us, bench 4.608us, regs 56) — FINAL.
//
//   u = Rz(tz)Ry(ty)Rx(tx)  =>  u^dag Z u = cx*cy*Z + cy*sx*Y - sy*X
//   Real encoded rows:  Z_t = (cx*cy*d_t - 2*sy*c_t) / n2
//   phi_i = (pi/6)(sum_t Zq_i[t] + sum_t Zq_i[t]*Zk0[t])
//   Zout_t = ( c^2*PZ_t + c*s*PY_t - s*PX_t ) / n2_v , (c,s)=cos/sin(phi/2)
//   P*_t = G00*dv_t + 2*ReG01*cv_t,  G = uv_t^dag P uv_t
//   out[i,t] = (Zout_t + 1)/2 ;  Sk = Sv = 1 in fp32.

#define W_MUL 0.6324555320336759f
#define PI_F  3.14159265358979323846f

// d_t, c_t bilinears + squared norm for a row (abs applied inside)
__device__ __forceinline__ void dc_row(const float4 lo, const float4 hi,
                                       float d[3], float c[3], float* n2o) {
    float x[8] = { fabsf(lo.x), fabsf(lo.y), fabsf(lo.z), fabsf(lo.w),
                   fabsf(hi.x), fabsf(hi.y), fabsf(hi.z), fabsf(hi.w) };
    float n2 = 0.f;
    #pragma unroll
    for (int a = 0; a < 8; a++) n2 += x[a] * x[a];
    *n2o = n2;
    #pragma unroll
    for (int t = 0; t < 3; t++) {
        int s = 1 << (2 - t);
        float dd = 0.f, cc = 0.f;
        #pragma unroll
        for (int a = 0; a < 8; a++) {
            if (a & s) continue;
            dd += x[a] * x[a] - x[a + s] * x[a + s];
            cc += x[a] * x[a + s];
        }
        d[t] = dd; c[t] = cc;
    }
}

// Z_t from bilinears and per-qubit (tx, ty) angle pairs (pre-scaled)
__device__ __forceinline__ void z_from_dc(const float d[3], const float c[3],
                                          float n2, const float tx[3],
                                          const float ty[3], float Z[3]) {
    float inv2 = __frcp_rn(n2);
    #pragma unroll
    for (int t = 0; t < 3; t++) {
        float cx = __cosf(tx[t]);
        float sy, cy;
        __sincosf(ty[t], &sy, &cy);
        Z[t] = (cx * cy * d[t] - 2.f * sy * c[t]) * inv2;
    }
}

__global__ void __launch_bounds__(32, 1)
qattn_kernel(const float* __restrict__ q,
             const float* __restrict__ k,
             const float* __restrict__ v,
             const float* __restrict__ wq,
             const float* __restrict__ wk,
             const float* __restrict__ wv,
             float* __restrict__ out) {
    int lane = threadIdx.x;
    if (lane >= 16) return;
    int i = lane >> 2;            // query row (cheap shift — q address ready early)
    int t = lane & 3;             // output qubit; t==3 is a pad lane
    int tl = t < 3 ? t : 2;       // clamp for safe wv loads

    // ---- issue ALL global loads back-to-back (max MLP, one round-trip) ----
    const float4* q4  = (const float4*)(q + i * 8);
    const float4* k4  = (const float4*)k;
    const float4* v4  = (const float4*)v;
    const float4* wq4 = (const float4*)wq;   // indices 0..7 (8 = wz[2], unused)
    const float4* wk4 = (const float4*)wk;
    float4 qlo = __ldg(q4),  qhi = __ldg(q4 + 1);
    float4 klo = __ldg(k4),  khi = __ldg(k4 + 1);
    float4 vlo = __ldg(v4),  vhi = __ldg(v4 + 1);
    float4 wqa = __ldg(wq4), wqb = __ldg(wq4 + 1);
    float4 wka = __ldg(wk4), wkb = __ldg(wk4 + 1);
    float  wvx = __ldg(wv + 3 * tl)     * W_MUL;
    float  wvy = __ldg(wv + 3 * tl + 1) * W_MUL;
    float  wvz = __ldg(wv + 3 * tl + 2) * W_MUL;

    // per-qubit (tx, ty) only — wz never enters a Z expectation
    float qtx[3] = { wqa.x * W_MUL, wqa.w * W_MUL, wqb.z * W_MUL };
    float qty[3] = { wqa.y * W_MUL, wqb.x * W_MUL, wqb.w * W_MUL };
    float ktx[3] = { wka.x * W_MUL, wka.w * W_MUL, wkb.z * W_MUL };
    float kty[3] = { wka.y * W_MUL, wkb.x * W_MUL, wkb.w * W_MUL };

    // ---- phi critical path: Zq, Zk -> phi_i -> sincos ----
    float dq[3], cq[3], nq2, dk[3], ck[3], nk2;
    dc_row(qlo, qhi, dq, cq, &nq2);
    dc_row(klo, khi, dk, ck, &nk2);
    float Zq[3], Zk[3];
    z_from_dc(dq, cq, nq2, qtx, qty, Zq);
    z_from_dc(dk, ck, nk2, ktx, kty, Zk);
    float phi = (PI_F / 6.f) * (Zq[0] + Zq[1] + Zq[2]
                                + Zq[0] * Zk[0] + Zq[1] * Zk[1] + Zq[2] * Zk[2]);
    float sh, ch;
    __sincosf(phi * 0.5f, &sh, &ch);

    // ---- phi-independent v-side (overlaps under the phi chain) ----
    float dv[3], cv[3], nv2;
    dc_row(vlo, vhi, dv, cv, &nv2);

    // u = Rz(wvz)Ry(wvy)Rx(wvx);  G = u^dag P u on qubit t
    float c0, s0, c1, s1, c2r, s2r;
    __sincosf(wvx * 0.5f, &s0, &c0);
    __sincosf(wvy * 0.5f, &s1, &c1);
    __sincosf(wvz * 0.5f, &s2r, &c2r);
    float M00r =  c1 * c0, M00i =  s1 * s0;
    float M01r = -s1 * c0, M01i = -c1 * s0;
    float M10r =  s1 * c0, M10i = -c1 * s0;
    float M11r =  c1 * c0, M11i = -s1 * s0;
    float u00r = c2r * M00r + s2r * M00i, u00i = -s2r * M00r + c2r * M00i;
    float u01r = c2r * M01r + s2r * M01i, u01i = -s2r * M01r + c2r * M01i;
    float u10r = c2r * M10r - s2r * M10i, u10i =  s2r * M10r + c2r * M10i;
    float u11r = c2r * M11r - s2r * M11i, u11i =  s2r * M11r + c2r * M11i;

    float gz00  = (u00r * u00r + u00i * u00i) - (u10r * u10r + u10i * u10i);
    float gz01r = (u00r * u01r + u00i * u01i) - (u10r * u11r + u10i * u11i);
    float gx00  = 2.f * (u00r * u10r + u00i * u10i);
    float gx01r = (u00r * u11r + u00i * u11i) + (u10r * u01r + u10i * u01i);
    float gy00  = 2.f * (u00r * u10i - u00i * u10r);
    float gy01r = (u00r * u11i - u00i * u11r) - (u10r * u01i - u10i * u01r);

    float inv2v = __frcp_rn(nv2);
    float PZ = (gz00 * dv[tl] + 2.f * gz01r * cv[tl]) * inv2v;
    float PY = (gy00 * dv[tl] + 2.f * gy01r * cv[tl]) * inv2v;
    float PX = (gx00 * dv[tl] + 2.f * gx01r * cv[tl]) * inv2v;

    // ---- tail: 3 FMA, store ----
    float z = ch * ch * PZ + ch * sh * PY - sh * PX;
    if (t < 3)
        out[i * 3 + t] = fmaf(z, 0.5f, 0.5f);
}

extern "C" void kernel_launch(void* const* d_in, const int* in_sizes, int n_in,
                              void* d_out, int out_size) {
    const float* q  = (const float*)d_in[0];
    const float* k  = (const float*)d_in[1];
    const float* v  = (const float*)d_in[2];
    const float* wq = (const float*)d_in[3];
    const float* wk = (const float*)d_in[4];
    const float* wv = (const float*)d_in[5];
    float* out = (float*)d_out;
    qattn_kernel<<<1, 32>>>(q, k, v, wq, wk, wv, out);
}

// round 13
// speedup vs baseline: 1.5141x; 1.5141x over previous
#include <cuda_runtime.h>
#include <math.h>

// Q_MultiHeadedAttention: quantum attention collapsed to 2x2 Heisenberg
// algebra. 16 lanes: i = lane>>2 (query row 0..3), t = lane&3 (output qubit,
// t==3 pads). No cross-lane communication (R6 showed SHFL on the critical
// path regresses at this launch-floor-bound scale). Session-best measured
// configuration (ncu 3.840us min, bench 4.608us min, regs 56) — FINAL.
//
//   u = Rz(tz)Ry(ty)Rx(tx)  =>  u^dag Z u = cx*cy*Z + cy*sx*Y - sy*X
//   Real encoded rows:  Z_t = (cx*cy*d_t - 2*sy*c_t) / n2
//   phi_i = (pi/6)(sum_t Zq_i[t] + sum_t Zq_i[t]*Zk0[t])
//   Zout_t = ( c^2*PZ_t + c*s*PY_t - s*PX_t ) / n2_v , (c,s)=cos/sin(phi/2)
//   P*_t = G00*dv_t + 2*ReG01*cv_t,  G = uv_t^dag P uv_t
//   out[i,t] = (Zout_t + 1)/2 ;  Sk = Sv = 1 in fp32.

#define W_MUL 0.6324555320336759f
#define PI_F  3.14159265358979323846f

// d_t, c_t bilinears + squared norm for a row (abs applied inside)
__device__ __forceinline__ void dc_row(const float4 lo, const float4 hi,
                                       float d[3], float c[3], float* n2o) {
    float x[8] = { fabsf(lo.x), fabsf(lo.y), fabsf(lo.z), fabsf(lo.w),
                   fabsf(hi.x), fabsf(hi.y), fabsf(hi.z), fabsf(hi.w) };
    float n2 = 0.f;
    #pragma unroll
    for (int a = 0; a < 8; a++) n2 += x[a] * x[a];
    *n2o = n2;
    #pragma unroll
    for (int t = 0; t < 3; t++) {
        int s = 1 << (2 - t);
        float dd = 0.f, cc = 0.f;
        #pragma unroll
        for (int a = 0; a < 8; a++) {
            if (a & s) continue;
            dd += x[a] * x[a] - x[a + s] * x[a + s];
            cc += x[a] * x[a + s];
        }
        d[t] = dd; c[t] = cc;
    }
}

// Z_t from bilinears and per-qubit (tx, ty) angle pairs (pre-scaled)
__device__ __forceinline__ void z_from_dc(const float d[3], const float c[3],
                                          float n2, const float tx[3],
                                          const float ty[3], float Z[3]) {
    float inv2 = __frcp_rn(n2);
    #pragma unroll
    for (int t = 0; t < 3; t++) {
        float cx = __cosf(tx[t]);
        float sy, cy;
        __sincosf(ty[t], &sy, &cy);
        Z[t] = (cx * cy * d[t] - 2.f * sy * c[t]) * inv2;
    }
}

__global__ void __launch_bounds__(32, 1)
qattn_kernel(const float* __restrict__ q,
             const float* __restrict__ k,
             const float* __restrict__ v,
             const float* __restrict__ wq,
             const float* __restrict__ wk,
             const float* __restrict__ wv,
             float* __restrict__ out) {
    int lane = threadIdx.x;
    if (lane >= 16) return;
    int i = lane >> 2;            // query row (cheap shift — q address ready early)
    int t = lane & 3;             // output qubit; t==3 is a pad lane
    int tl = t < 3 ? t : 2;       // clamp for safe wv loads

    // ---- issue ALL global loads back-to-back (max MLP, one round-trip) ----
    const float4* q4  = (const float4*)(q + i * 8);
    const float4* k4  = (const float4*)k;
    const float4* v4  = (const float4*)v;
    const float4* wq4 = (const float4*)wq;   // indices 0..7 (8 = wz[2], unused)
    const float4* wk4 = (const float4*)wk;
    float4 qlo = __ldg(q4),  qhi = __ldg(q4 + 1);
    float4 klo = __ldg(k4),  khi = __ldg(k4 + 1);
    float4 vlo = __ldg(v4),  vhi = __ldg(v4 + 1);
    float4 wqa = __ldg(wq4), wqb = __ldg(wq4 + 1);
    float4 wka = __ldg(wk4), wkb = __ldg(wk4 + 1);
    float  wvx = __ldg(wv + 3 * tl)     * W_MUL;
    float  wvy = __ldg(wv + 3 * tl + 1) * W_MUL;
    float  wvz = __ldg(wv + 3 * tl + 2) * W_MUL;

    // per-qubit (tx, ty) only — wz never enters a Z expectation
    float qtx[3] = { wqa.x * W_MUL, wqa.w * W_MUL, wqb.z * W_MUL };
    float qty[3] = { wqa.y * W_MUL, wqb.x * W_MUL, wqb.w * W_MUL };
    float ktx[3] = { wka.x * W_MUL, wka.w * W_MUL, wkb.z * W_MUL };
    float kty[3] = { wka.y * W_MUL, wkb.x * W_MUL, wkb.w * W_MUL };

    // ---- phi critical path: Zq, Zk -> phi_i -> sincos ----
    float dq[3], cq[3], nq2, dk[3], ck[3], nk2;
    dc_row(qlo, qhi, dq, cq, &nq2);
    dc_row(klo, khi, dk, ck, &nk2);
    float Zq[3], Zk[3];
    z_from_dc(dq, cq, nq2, qtx, qty, Zq);
    z_from_dc(dk, ck, nk2, ktx, kty, Zk);
    float phi = (PI_F / 6.f) * (Zq[0] + Zq[1] + Zq[2]
                                + Zq[0] * Zk[0] + Zq[1] * Zk[1] + Zq[2] * Zk[2]);
    float sh, ch;
    __sincosf(phi * 0.5f, &sh, &ch);

    // ---- phi-independent v-side (overlaps under the phi chain) ----
    float dv[3], cv[3], nv2;
    dc_row(vlo, vhi, dv, cv, &nv2);

    // u = Rz(wvz)Ry(wvy)Rx(wvx);  G = u^dag P u on qubit t
    float c0, s0, c1, s1, c2r, s2r;
    __sincosf(wvx * 0.5f, &s0, &c0);
    __sincosf(wvy * 0.5f, &s1, &c1);
    __sincosf(wvz * 0.5f, &s2r, &c2r);
    float M00r =  c1 * c0, M00i =  s1 * s0;
    float M01r = -s1 * c0, M01i = -c1 * s0;
    float M10r =  s1 * c0, M10i = -c1 * s0;
    float M11r =  c1 * c0, M11i = -s1 * s0;
    float u00r = c2r * M00r + s2r * M00i, u00i = -s2r * M00r + c2r * M00i;
    float u01r = c2r * M01r + s2r * M01i, u01i = -s2r * M01r + c2r * M01i;
    float u10r = c2r * M10r - s2r * M10i, u10i =  s2r * M10r + c2r * M10i;
    float u11r = c2r * M11r - s2r * M11i, u11i =  s2r * M11r + c2r * M11i;

    float gz00  = (u00r * u00r + u00i * u00i) - (u10r * u10r + u10i * u10i);
    float gz01r = (u00r * u01r + u00i * u01i) - (u10r * u11r + u10i * u11i);
    float gx00  = 2.f * (u00r * u10r + u00i * u10i);
    float gx01r = (u00r * u11r + u00i * u11i) + (u10r * u01r + u10i * u01i);
    float gy00  = 2.f * (u00r * u10i - u00i * u10r);
    float gy01r = (u00r * u11i - u00i * u11r) - (u10r * u01i - u10i * u01r);

    float inv2v = __frcp_rn(nv2);
    float PZ = (gz00 * dv[tl] + 2.f * gz01r * cv[tl]) * inv2v;
    float PY = (gy00 * dv[tl] + 2.f * gy01r * cv[tl]) * inv2v;
    float PX = (gx00 * dv[tl] + 2.f * gx01r * cv[tl]) * inv2v;

    // ---- tail: 3 FMA, store ----
    float z = ch * ch * PZ + ch * sh * PY - sh * PX;
    if (t < 3)
        out[i * 3 + t] = fmaf(z, 0.5f, 0.5f);
}

extern "C" void kernel_launch(void* const* d_in, const int* in_sizes, int n_in,
                              void* d_out, int out_size) {
    const float* q  = (const float*)d_in[0];
    const float* k  = (const float*)d_in[1];
    const float* v  = (const float*)d_in[2];
    const float* wq = (const float*)d_in[3];
    const float* wk = (const float*)d_in[4];
    const float* wv = (const float*)d_in[5];
    float* out = (float*)d_out;
    qattn_kernel<<<1, 32>>>(q, k, v, wq, wk, wv, out);
}